// round 11
// baseline (speedup 1.0000x reference)
#include <cuda_runtime.h>
#include <math.h>

// Problem constants
#define Bb 2
#define LL 2048
#define EE 512
#define HH 8
#define DD 64
#define NWORDS (LL/32)

// Scratch (device globals -- no allocation allowed)
__device__ float g_q[Bb*HH*LL*DD];
__device__ float g_k[Bb*HH*LL*DD];
__device__ float g_v[Bb*HH*LL*DD];
__device__ float g_o[Bb*LL*EE];
__device__ unsigned int g_mb[Bb*LL*NWORDS];

// ---------------------------------------------------------------------------
// Packed fp32x2 helpers
// ---------------------------------------------------------------------------
typedef unsigned long long u64;

__device__ __forceinline__ u64 pack2(float lo, float hi) {
    u64 r; asm("mov.b64 %0, {%1, %2};" : "=l"(r) : "f"(lo), "f"(hi)); return r;
}
__device__ __forceinline__ void unpack2(u64 v, float &lo, float &hi) {
    asm("mov.b64 {%0, %1}, %2;" : "=f"(lo), "=f"(hi) : "l"(v));
}
__device__ __forceinline__ u64 ffma2(u64 a, u64 b, u64 c) {
    u64 d; asm("fma.rn.f32x2 %0, %1, %2, %3;" : "=l"(d) : "l"(a), "l"(b), "l"(c)); return d;
}
__device__ __forceinline__ u64 fadd2(u64 a, u64 b) {
    u64 d; asm("add.rn.f32x2 %0, %1, %2;" : "=l"(d) : "l"(a), "l"(b)); return d;
}
__device__ __forceinline__ u64 fmul2(u64 a, u64 b) {
    u64 d; asm("mul.rn.f32x2 %0, %1, %2;" : "=l"(d) : "l"(a), "l"(b)); return d;
}
__device__ __forceinline__ float ex2f(float x) {
    float y; asm("ex2.approx.f32 %0, %1;" : "=f"(y) : "f"(x)); return y;
}
__device__ __forceinline__ void cp16(unsigned int d, const float* s) {
    asm volatile("cp.async.cg.shared.global [%0], [%1], 16;" :: "r"(d), "l"(s));
}

// ---------------------------------------------------------------------------
// Pack mask [B,1,L,L] int32 -> bitmask words via warp ballot
// ---------------------------------------------------------------------------
__global__ void pack_mask_kernel(const int* __restrict__ mask) {
    int idx = blockIdx.x * blockDim.x + threadIdx.x;
    unsigned int bit = (mask[idx] != 0) ? 1u : 0u;
    unsigned int word = __ballot_sync(0xffffffffu, bit);
    if ((threadIdx.x & 31) == 0) g_mb[idx >> 5] = word;
}

// ---------------------------------------------------------------------------
// GEMM (proven 60.3us): C = A @ W^T + bias. M=4096 N=512 K=512.
// 128x64 CTA tile, 256 threads, 8x4 microtile (rows packed fp32x2).
// ---------------------------------------------------------------------------
#define GM 4096
#define GN 512
#define GK 512
#define BMt 128
#define BNt 64
#define BKT 16
#define LDA 132   // BMt + 4 pad
#define LDW 68    // BNt + 4 pad

__device__ __forceinline__ void gemm_body(
    const float* __restrict__ Ap, const float* __restrict__ W,
    const float* __restrict__ bias, float* __restrict__ Cp, bool headsplit)
{
    __shared__ float As[BKT][LDA];
    __shared__ float Ws[BKT][LDW];

    int tid = threadIdx.x;
    int tx = tid % 16;          // col group (4 cols)
    int ty = tid / 16;          // row group (8 rows)
    int m0 = blockIdx.y * BMt;
    int n0 = blockIdx.x * BNt;

    int lrA = tid >> 1;         // 0..127
    int lkA = (tid & 1) * 8;    // 0 or 8
    int lrW = tid >> 2;         // 0..63
    int lkW = (tid & 3) * 4;    // 0,4,8,12

    const float* aSrc = &Ap[(size_t)(m0 + lrA) * GK + lkA];
    const float* wSrc = &W [(size_t)(n0 + lrW) * GK + lkW];

    float4 ra0 = *(const float4*)(aSrc + 0);
    float4 ra1 = *(const float4*)(aSrc + 4);
    float4 rw0 = *(const float4*)(wSrc + 0);

    u64 acc[4][4];
    #pragma unroll
    for (int i = 0; i < 4; i++)
        #pragma unroll
        for (int j = 0; j < 4; j++) acc[i][j] = 0ull;

    for (int k0 = 0; k0 < GK; k0 += BKT) {
        As[lkA+0][lrA] = ra0.x; As[lkA+1][lrA] = ra0.y; As[lkA+2][lrA] = ra0.z; As[lkA+3][lrA] = ra0.w;
        As[lkA+4][lrA] = ra1.x; As[lkA+5][lrA] = ra1.y; As[lkA+6][lrA] = ra1.z; As[lkA+7][lrA] = ra1.w;
        Ws[lkW+0][lrW] = rw0.x; Ws[lkW+1][lrW] = rw0.y; Ws[lkW+2][lrW] = rw0.z; Ws[lkW+3][lrW] = rw0.w;
        __syncthreads();

        if (k0 + BKT < GK) {
            ra0 = *(const float4*)(aSrc + k0 + BKT + 0);
            ra1 = *(const float4*)(aSrc + k0 + BKT + 4);
            rw0 = *(const float4*)(wSrc + k0 + BKT);
        }

        #pragma unroll
        for (int kk = 0; kk < BKT; kk++) {
            ulonglong2 aA = *(const ulonglong2*)&As[kk][ty * 8];
            ulonglong2 aB = *(const ulonglong2*)&As[kk][ty * 8 + 4];
            float4 w4 = *(const float4*)&Ws[kk][tx * 4];
            u64 a[4] = {aA.x, aA.y, aB.x, aB.y};
            u64 w[4];
            w[0] = pack2(w4.x, w4.x); w[1] = pack2(w4.y, w4.y);
            w[2] = pack2(w4.z, w4.z); w[3] = pack2(w4.w, w4.w);
            #pragma unroll
            for (int i = 0; i < 4; i++)
                #pragma unroll
                for (int j = 0; j < 4; j++)
                    acc[i][j] = ffma2(a[i], w[j], acc[i][j]);
        }
        __syncthreads();
    }

    #pragma unroll
    for (int j = 0; j < 4; j++) {
        int n = n0 + tx * 4 + j;
        float bval = bias[n];
        int h = n / DD, d = n % DD;
        #pragma unroll
        for (int i = 0; i < 4; i++) {
            float vlo, vhi;
            unpack2(acc[i][j], vlo, vhi);
            int m = m0 + ty * 8 + 2 * i;
            if (headsplit) {
                int b = m / LL, l = m % LL;
                size_t base = (((size_t)(b * HH + h)) * LL + l) * DD + d;
                Cp[base]      = vlo + bval;
                Cp[base + DD] = vhi + bval;
            } else {
                Cp[(size_t)m * GN + n]       = vlo + bval;
                Cp[(size_t)(m + 1) * GN + n] = vhi + bval;
            }
        }
    }
}

__global__ __launch_bounds__(256, 2) void qkv_gemm_kernel(
    const float* __restrict__ values, const float* __restrict__ keysp,
    const float* __restrict__ query,
    const float* __restrict__ Wv, const float* __restrict__ bv,
    const float* __restrict__ Wk, const float* __restrict__ bk,
    const float* __restrict__ Wq, const float* __restrict__ bq)
{
    int z = blockIdx.z;
    const float* A    = (z == 0) ? values : (z == 1) ? keysp : query;
    const float* W    = (z == 0) ? Wv : (z == 1) ? Wk : Wq;
    const float* bias = (z == 0) ? bv : (z == 1) ? bk : bq;
    float* C          = (z == 0) ? g_v : (z == 1) ? g_k : g_q;
    gemm_body(A, W, bias, C, true);
}

__global__ __launch_bounds__(256, 2) void out_gemm_kernel(
    const float* __restrict__ Wo, const float* __restrict__ bo, float* __restrict__ C)
{
    gemm_body(g_o, Wo, bo, C, false);
}

// ---------------------------------------------------------------------------
// Fused flash attention. R10 structure, with the score buffer halved to s[16]
// (two softmax batches per 32-key tile) so regs fit 3 CTAs/SM (12 warps/SM,
// was 8) -- occupancy is the binding constraint per ncu (issue 47% of FMA
// floor at 2 warps/SMSP).
// ---------------------------------------------------------------------------
#define BQ 128
#define BKK 32
#define NT (LL/BKK)
#define SCALE2   (0.04419417382415922f * 1.4426950408889634f)  // log2e/sqrt(512)
#define MASKVAL2 (-1e20f * 0.04419417382415922f * 1.4426950408889634f)

__global__ __launch_bounds__(128, 3) void attn_kernel()
{
    __shared__ float Ks[2][BKK][DD];
    __shared__ float Vs[2][BKK][DD];

    int r  = threadIdx.x;
    int bh = blockIdx.y;
    int b  = bh / HH;
    int h  = bh % HH;
    int qi = blockIdx.x * BQ + r;

    const u64* qptr = (const u64*)(g_q + ((size_t)bh * LL + qi) * DD);
    u64 sc2 = pack2(SCALE2, SCALE2);
    u64 q2[32];
    #pragma unroll
    for (int i = 0; i < 32; i++) q2[i] = fmul2(qptr[i], sc2);

    u64 o2[32];
    #pragma unroll
    for (int i = 0; i < 32; i++) o2[i] = 0ull;

    float m = -1e30f, l = 0.f;

    const unsigned int* mrow = g_mb + ((size_t)b * LL + qi) * NWORDS;
    const float* kbase = g_k + (size_t)bh * LL * DD;
    const float* vbase = g_v + (size_t)bh * LL * DD;

    unsigned int kd0 = (unsigned int)__cvta_generic_to_shared(&Ks[0][0][0]);
    unsigned int vd0 = (unsigned int)__cvta_generic_to_shared(&Vs[0][0][0]);

    // prefetch tile 0 -> buffer 0
    #pragma unroll
    for (int i = 0; i < 4; i++) {
        int idx = r + i * 128;
        cp16(kd0 + idx * 16, kbase + idx * 4);
        cp16(vd0 + idx * 16, vbase + idx * 4);
    }
    asm volatile("cp.async.commit_group;");

    for (int t = 0; t < NT; t++) {
        __syncthreads();
        if (t + 1 < NT) {
            int nb = (t + 1) & 1;
            unsigned int kd = kd0 + nb * (BKK * DD * 4);
            unsigned int vd = vd0 + nb * (BKK * DD * 4);
            const float* kg = kbase + (size_t)(t + 1) * BKK * DD;
            const float* vg = vbase + (size_t)(t + 1) * BKK * DD;
            #pragma unroll
            for (int i = 0; i < 4; i++) {
                int idx = r + i * 128;
                cp16(kd + idx * 16, kg + idx * 4);
                cp16(vd + idx * 16, vg + idx * 4);
            }
            asm volatile("cp.async.commit_group;");
            asm volatile("cp.async.wait_group 1;");
        } else {
            asm volatile("cp.async.wait_group 0;");
        }
        __syncthreads();

        int cb = t & 1;
        unsigned int word = mrow[t];

        #pragma unroll
        for (int batch = 0; batch < 2; batch++) {
            float s[16];
            float tmax = -3.0e38f;
            #pragma unroll
            for (int kk = 0; kk < 16; kk++) {
                int key = batch * 16 + kk;
                const ulonglong2* kr = (const ulonglong2*)&Ks[cb][key][0];
                u64 a0 = 0ull, a1 = 0ull, a2 = 0ull, a3 = 0ull;
                #pragma unroll
                for (int i = 0; i < 8; i++) {
                    ulonglong2 kv0 = kr[2 * i];
                    ulonglong2 kv1 = kr[2 * i + 1];
                    a0 = ffma2(q2[4 * i + 0], kv0.x, a0);
                    a1 = ffma2(q2[4 * i + 1], kv0.y, a1);
                    a2 = ffma2(q2[4 * i + 2], kv1.x, a2);
                    a3 = ffma2(q2[4 * i + 3], kv1.y, a3);
                }
                u64 ap = fadd2(fadd2(a0, a1), fadd2(a2, a3));
                float alo, ahi;
                unpack2(ap, alo, ahi);
                float acc = alo + ahi;
                float sv = ((word >> key) & 1u) ? acc : MASKVAL2;
                s[kk] = sv;
                tmax = fmaxf(tmax, sv);
            }
            float mnew = fmaxf(m, tmax);
            if (mnew > m) {                 // skip rescale when max unchanged
                float corr = ex2f(m - mnew);
                l *= corr;
                u64 corr2 = pack2(corr, corr);
                #pragma unroll
                for (int i = 0; i < 32; i++) o2[i] = fmul2(o2[i], corr2);
                m = mnew;
            }
            #pragma unroll
            for (int kk = 0; kk < 16; kk++) {
                int key = batch * 16 + kk;
                float p = ex2f(s[kk] - m);
                l += p;
                u64 pp = pack2(p, p);
                const ulonglong2* vr = (const ulonglong2*)&Vs[cb][key][0];
                #pragma unroll
                for (int i = 0; i < 8; i++) {
                    ulonglong2 v0 = vr[2 * i];
                    ulonglong2 v1 = vr[2 * i + 1];
                    o2[4 * i + 0] = ffma2(pp, v0.x, o2[4 * i + 0]);
                    o2[4 * i + 1] = ffma2(pp, v0.y, o2[4 * i + 1]);
                    o2[4 * i + 2] = ffma2(pp, v1.x, o2[4 * i + 2]);
                    o2[4 * i + 3] = ffma2(pp, v1.y, o2[4 * i + 3]);
                }
            }
        }
    }

    float inv = 1.f / l;
    u64 inv2 = pack2(inv, inv);
    ulonglong2* optr = (ulonglong2*)(g_o + ((size_t)(b * LL + qi)) * EE + h * DD);
    #pragma unroll
    for (int i = 0; i < 16; i++) {
        ulonglong2 ov;
        ov.x = fmul2(o2[2 * i + 0], inv2);
        ov.y = fmul2(o2[2 * i + 1], inv2);
        optr[i] = ov;
    }
}

// ---------------------------------------------------------------------------
// kernel_launch
// ---------------------------------------------------------------------------
extern "C" void kernel_launch(void* const* d_in, const int* in_sizes, int n_in,
                              void* d_out, int out_size)
{
    const float* values = (const float*)d_in[0];
    const float* keys   = (const float*)d_in[1];
    const float* query  = (const float*)d_in[2];
    const int*   mask   = (const int*)d_in[3];
    const float* Wv = (const float*)d_in[4];
    const float* bv = (const float*)d_in[5];
    const float* Wk = (const float*)d_in[6];
    const float* bk = (const float*)d_in[7];
    const float* Wq = (const float*)d_in[8];
    const float* bq = (const float*)d_in[9];
    const float* Wo = (const float*)d_in[10];
    const float* bo = (const float*)d_in[11];
    float* out = (float*)d_out;

    pack_mask_kernel<<<(Bb * LL * LL) / 256, 256>>>(mask);

    dim3 qkv_grid(GN / BNt, GM / BMt, 3);    // (8, 32, 3) = 768 CTAs
    qkv_gemm_kernel<<<qkv_grid, 256>>>(values, keys, query, Wv, bv, Wk, bk, Wq, bq);

    attn_kernel<<<dim3(LL / BQ, Bb * HH), 128>>>();   // 256 CTAs

    dim3 o_grid(GN / BNt, GM / BMt);         // (8, 32) = 256 CTAs
    out_gemm_kernel<<<o_grid, 256>>>(Wo, bo, out);
}

// round 14
// speedup vs baseline: 1.3296x; 1.3296x over previous
#include <cuda_runtime.h>
#include <math.h>

// Problem constants
#define Bb 2
#define LL 2048
#define EE 512
#define HH 8
#define DD 64
#define NWORDS (LL/32)
#define RTOT (Bb*HH*LL)             // 32768 attention rows
#define SPLIT 4
#define KEYS_PER_SPLIT (LL/SPLIT)   // 512

// Scratch (device globals -- no allocation allowed)
__device__ float g_q[Bb*HH*LL*DD];
__device__ float g_k[Bb*HH*LL*DD];
__device__ float g_v[Bb*HH*LL*DD];
__device__ float g_o[Bb*LL*EE];
__device__ unsigned int g_mb[Bb*LL*NWORDS];
// split-KV partials (unnormalized o, running max m (log2 domain), denom l)
__device__ float g_po[SPLIT*RTOT*DD];
__device__ float g_pm[SPLIT*RTOT];
__device__ float g_pl[SPLIT*RTOT];

// ---------------------------------------------------------------------------
// Packed fp32x2 helpers
// ---------------------------------------------------------------------------
typedef unsigned long long u64;

__device__ __forceinline__ u64 pack2(float lo, float hi) {
    u64 r; asm("mov.b64 %0, {%1, %2};" : "=l"(r) : "f"(lo), "f"(hi)); return r;
}
__device__ __forceinline__ void unpack2(u64 v, float &lo, float &hi) {
    asm("mov.b64 {%0, %1}, %2;" : "=f"(lo), "=f"(hi) : "l"(v));
}
__device__ __forceinline__ u64 ffma2(u64 a, u64 b, u64 c) {
    u64 d; asm("fma.rn.f32x2 %0, %1, %2, %3;" : "=l"(d) : "l"(a), "l"(b), "l"(c)); return d;
}
__device__ __forceinline__ u64 fadd2(u64 a, u64 b) {
    u64 d; asm("add.rn.f32x2 %0, %1, %2;" : "=l"(d) : "l"(a), "l"(b)); return d;
}
__device__ __forceinline__ u64 fmul2(u64 a, u64 b) {
    u64 d; asm("mul.rn.f32x2 %0, %1, %2;" : "=l"(d) : "l"(a), "l"(b)); return d;
}
__device__ __forceinline__ float ex2f(float x) {
    float y; asm("ex2.approx.f32 %0, %1;" : "=f"(y) : "f"(x)); return y;
}
__device__ __forceinline__ void cp16(unsigned int d, const float* s) {
    asm volatile("cp.async.cg.shared.global [%0], [%1], 16;" :: "r"(d), "l"(s));
}

// ---------------------------------------------------------------------------
// Pack mask [B,1,L,L] int32 -> bitmask words via warp ballot
// ---------------------------------------------------------------------------
__global__ void pack_mask_kernel(const int* __restrict__ mask) {
    int idx = blockIdx.x * blockDim.x + threadIdx.x;
    unsigned int bit = (mask[idx] != 0) ? 1u : 0u;
    unsigned int word = __ballot_sync(0xffffffffu, bit);
    if ((threadIdx.x & 31) == 0) g_mb[idx >> 5] = word;
}

// ---------------------------------------------------------------------------
// GEMM (proven 60.3us): C = A @ W^T + bias. M=4096 N=512 K=512.
// 128x64 CTA tile, 256 threads, 8x4 microtile (rows packed fp32x2).
// ---------------------------------------------------------------------------
#define GM 4096
#define GN 512
#define GK 512
#define BMt 128
#define BNt 64
#define BKT 16
#define LDA 132   // BMt + 4 pad
#define LDW 68    // BNt + 4 pad

__device__ __forceinline__ void gemm_body(
    const float* __restrict__ Ap, const float* __restrict__ W,
    const float* __restrict__ bias, float* __restrict__ Cp, bool headsplit)
{
    __shared__ float As[BKT][LDA];
    __shared__ float Ws[BKT][LDW];

    int tid = threadIdx.x;
    int tx = tid % 16;          // col group (4 cols)
    int ty = tid / 16;          // row group (8 rows)
    int m0 = blockIdx.y * BMt;
    int n0 = blockIdx.x * BNt;

    int lrA = tid >> 1;         // 0..127
    int lkA = (tid & 1) * 8;    // 0 or 8
    int lrW = tid >> 2;         // 0..63
    int lkW = (tid & 3) * 4;    // 0,4,8,12

    const float* aSrc = &Ap[(size_t)(m0 + lrA) * GK + lkA];
    const float* wSrc = &W [(size_t)(n0 + lrW) * GK + lkW];

    float4 ra0 = *(const float4*)(aSrc + 0);
    float4 ra1 = *(const float4*)(aSrc + 4);
    float4 rw0 = *(const float4*)(wSrc + 0);

    u64 acc[4][4];
    #pragma unroll
    for (int i = 0; i < 4; i++)
        #pragma unroll
        for (int j = 0; j < 4; j++) acc[i][j] = 0ull;

    for (int k0 = 0; k0 < GK; k0 += BKT) {
        As[lkA+0][lrA] = ra0.x; As[lkA+1][lrA] = ra0.y; As[lkA+2][lrA] = ra0.z; As[lkA+3][lrA] = ra0.w;
        As[lkA+4][lrA] = ra1.x; As[lkA+5][lrA] = ra1.y; As[lkA+6][lrA] = ra1.z; As[lkA+7][lrA] = ra1.w;
        Ws[lkW+0][lrW] = rw0.x; Ws[lkW+1][lrW] = rw0.y; Ws[lkW+2][lrW] = rw0.z; Ws[lkW+3][lrW] = rw0.w;
        __syncthreads();

        if (k0 + BKT < GK) {
            ra0 = *(const float4*)(aSrc + k0 + BKT + 0);
            ra1 = *(const float4*)(aSrc + k0 + BKT + 4);
            rw0 = *(const float4*)(wSrc + k0 + BKT);
        }

        #pragma unroll
        for (int kk = 0; kk < BKT; kk++) {
            ulonglong2 aA = *(const ulonglong2*)&As[kk][ty * 8];
            ulonglong2 aB = *(const ulonglong2*)&As[kk][ty * 8 + 4];
            float4 w4 = *(const float4*)&Ws[kk][tx * 4];
            u64 a[4] = {aA.x, aA.y, aB.x, aB.y};
            u64 w[4];
            w[0] = pack2(w4.x, w4.x); w[1] = pack2(w4.y, w4.y);
            w[2] = pack2(w4.z, w4.z); w[3] = pack2(w4.w, w4.w);
            #pragma unroll
            for (int i = 0; i < 4; i++)
                #pragma unroll
                for (int j = 0; j < 4; j++)
                    acc[i][j] = ffma2(a[i], w[j], acc[i][j]);
        }
        __syncthreads();
    }

    #pragma unroll
    for (int j = 0; j < 4; j++) {
        int n = n0 + tx * 4 + j;
        float bval = bias[n];
        int h = n / DD, d = n % DD;
        #pragma unroll
        for (int i = 0; i < 4; i++) {
            float vlo, vhi;
            unpack2(acc[i][j], vlo, vhi);
            int m = m0 + ty * 8 + 2 * i;
            if (headsplit) {
                int b = m / LL, l = m % LL;
                size_t base = (((size_t)(b * HH + h)) * LL + l) * DD + d;
                Cp[base]      = vlo + bval;
                Cp[base + DD] = vhi + bval;
            } else {
                Cp[(size_t)m * GN + n]       = vlo + bval;
                Cp[(size_t)(m + 1) * GN + n] = vhi + bval;
            }
        }
    }
}

__global__ __launch_bounds__(256, 2) void qkv_gemm_kernel(
    const float* __restrict__ values, const float* __restrict__ keysp,
    const float* __restrict__ query,
    const float* __restrict__ Wv, const float* __restrict__ bv,
    const float* __restrict__ Wk, const float* __restrict__ bk,
    const float* __restrict__ Wq, const float* __restrict__ bq)
{
    int z = blockIdx.z;
    const float* A    = (z == 0) ? values : (z == 1) ? keysp : query;
    const float* W    = (z == 0) ? Wv : (z == 1) ? Wk : Wq;
    const float* bias = (z == 0) ? bv : (z == 1) ? bk : bq;
    float* C          = (z == 0) ? g_v : (z == 1) ? g_k : g_q;
    gemm_body(A, W, bias, C, true);
}

__global__ __launch_bounds__(256, 2) void out_gemm_kernel(
    const float* __restrict__ Wo, const float* __restrict__ bo, float* __restrict__ C)
{
    gemm_body(g_o, Wo, bo, C, false);
}

// ---------------------------------------------------------------------------
// Split-KV flash attention. EXACT R10 inner loop (batched softmax, s[32],
// NO launch_bounds min -- the R11 reg cap caused spills). Each CTA covers
// 128 q rows x 512 keys; grid = 1024 CTAs (3.5 waves) fixes the R10 wave
// packing (256 CTAs = 0.86 waves, 40 SMs at 1 warp/SMSP).
// ---------------------------------------------------------------------------
#define BQ 128
#define BKK 32
#define NT (KEYS_PER_SPLIT/BKK)     // 16
#define SCALE2   (0.04419417382415922f * 1.4426950408889634f)  // log2e/sqrt(512)
#define MASKVAL2 (-1e20f * 0.04419417382415922f * 1.4426950408889634f)

__global__ __launch_bounds__(128) void attn_kernel()
{
    __shared__ float Ks[2][BKK][DD];
    __shared__ float Vs[2][BKK][DD];

    int r  = threadIdx.x;
    int bh = blockIdx.y;
    int sp = blockIdx.z;
    int b  = bh / HH;
    int qi = blockIdx.x * BQ + r;
    int k_start = sp * KEYS_PER_SPLIT;

    const u64* qptr = (const u64*)(g_q + ((size_t)bh * LL + qi) * DD);
    u64 sc2 = pack2(SCALE2, SCALE2);
    u64 q2[32];
    #pragma unroll
    for (int i = 0; i < 32; i++) q2[i] = fmul2(qptr[i], sc2);

    u64 o2[32];
    #pragma unroll
    for (int i = 0; i < 32; i++) o2[i] = 0ull;

    float m = -1e30f, l = 0.f;

    const unsigned int* mrow = g_mb + ((size_t)b * LL + qi) * NWORDS + (k_start >> 5);
    const float* kbase = g_k + ((size_t)bh * LL + k_start) * DD;
    const float* vbase = g_v + ((size_t)bh * LL + k_start) * DD;

    unsigned int kd0 = (unsigned int)__cvta_generic_to_shared(&Ks[0][0][0]);
    unsigned int vd0 = (unsigned int)__cvta_generic_to_shared(&Vs[0][0][0]);

    // prefetch tile 0 -> buffer 0
    #pragma unroll
    for (int i = 0; i < 4; i++) {
        int idx = r + i * 128;
        cp16(kd0 + idx * 16, kbase + idx * 4);
        cp16(vd0 + idx * 16, vbase + idx * 4);
    }
    asm volatile("cp.async.commit_group;");

    for (int t = 0; t < NT; t++) {
        __syncthreads();
        if (t + 1 < NT) {
            int nb = (t + 1) & 1;
            unsigned int kd = kd0 + nb * (BKK * DD * 4);
            unsigned int vd = vd0 + nb * (BKK * DD * 4);
            const float* kg = kbase + (size_t)(t + 1) * BKK * DD;
            const float* vg = vbase + (size_t)(t + 1) * BKK * DD;
            #pragma unroll
            for (int i = 0; i < 4; i++) {
                int idx = r + i * 128;
                cp16(kd + idx * 16, kg + idx * 4);
                cp16(vd + idx * 16, vg + idx * 4);
            }
            asm volatile("cp.async.commit_group;");
            asm volatile("cp.async.wait_group 1;");
        } else {
            asm volatile("cp.async.wait_group 0;");
        }
        __syncthreads();

        int cb = t & 1;
        unsigned int bits = mrow[t];

        float s[32];
        float tmax = -3.0e38f;
        #pragma unroll
        for (int kk = 0; kk < 32; kk++) {
            const ulonglong2* kr = (const ulonglong2*)&Ks[cb][kk][0];
            u64 a0 = 0ull, a1 = 0ull, a2 = 0ull, a3 = 0ull;
            #pragma unroll
            for (int i = 0; i < 8; i++) {
                ulonglong2 kv0 = kr[2 * i];
                ulonglong2 kv1 = kr[2 * i + 1];
                a0 = ffma2(q2[4 * i + 0], kv0.x, a0);
                a1 = ffma2(q2[4 * i + 1], kv0.y, a1);
                a2 = ffma2(q2[4 * i + 2], kv1.x, a2);
                a3 = ffma2(q2[4 * i + 3], kv1.y, a3);
            }
            u64 ap = fadd2(fadd2(a0, a1), fadd2(a2, a3));
            float alo, ahi;
            unpack2(ap, alo, ahi);
            float acc = alo + ahi;
            float sv = ((bits >> kk) & 1u) ? acc : MASKVAL2;
            s[kk] = sv;
            tmax = fmaxf(tmax, sv);
        }
        float mnew = fmaxf(m, tmax);
        if (mnew > m) {                 // skip rescale when max unchanged
            float corr = ex2f(m - mnew);
            l *= corr;
            u64 corr2 = pack2(corr, corr);
            #pragma unroll
            for (int i = 0; i < 32; i++) o2[i] = fmul2(o2[i], corr2);
            m = mnew;
        }
        #pragma unroll
        for (int kk = 0; kk < 32; kk++) {
            float p = ex2f(s[kk] - m);
            l += p;
            u64 pp = pack2(p, p);
            const ulonglong2* vr = (const ulonglong2*)&Vs[cb][kk][0];
            #pragma unroll
            for (int i = 0; i < 8; i++) {
                ulonglong2 v0 = vr[2 * i];
                ulonglong2 v1 = vr[2 * i + 1];
                o2[4 * i + 0] = ffma2(pp, v0.x, o2[4 * i + 0]);
                o2[4 * i + 1] = ffma2(pp, v0.y, o2[4 * i + 1]);
                o2[4 * i + 2] = ffma2(pp, v1.x, o2[4 * i + 2]);
                o2[4 * i + 3] = ffma2(pp, v1.y, o2[4 * i + 3]);
            }
        }
    }

    // write unnormalized partial (combine kernel normalizes)
    size_t pr = (size_t)sp * RTOT + (size_t)bh * LL + qi;
    g_pm[pr] = m;
    g_pl[pr] = l;
    u64* po = (u64*)g_po + pr * 32;
    #pragma unroll
    for (int i = 0; i < 32; i++) po[i] = o2[i];
}

// ---------------------------------------------------------------------------
// Combine SPLIT partials -> g_o [B, L, E]. One warp per row (9.6us measured).
// ---------------------------------------------------------------------------
__global__ __launch_bounds__(256) void combine_kernel()
{
    int warp = threadIdx.x >> 5;
    int lane = threadIdx.x & 31;
    int row = blockIdx.x * 8 + warp;          // over RTOT rows (bh*LL + q)

    float ms[SPLIT], ls[SPLIT];
    float mx = -3.0e38f;
    #pragma unroll
    for (int s = 0; s < SPLIT; s++) {
        ms[s] = g_pm[(size_t)s * RTOT + row];
        ls[s] = g_pl[(size_t)s * RTOT + row];
        mx = fmaxf(mx, ms[s]);
    }
    float den = 0.f;
    float cs[SPLIT];
    #pragma unroll
    for (int s = 0; s < SPLIT; s++) {
        cs[s] = ex2f(ms[s] - mx);
        den += ls[s] * cs[s];
    }
    float inv = 1.f / den;

    u64 acc = 0ull;
    #pragma unroll
    for (int s = 0; s < SPLIT; s++) {
        u64 ov = ((const u64*)g_po)[((size_t)s * RTOT + row) * 32 + lane];
        u64 c2 = pack2(cs[s], cs[s]);
        acc = ffma2(ov, c2, acc);
    }
    acc = fmul2(acc, pack2(inv, inv));

    int bh = row / LL, q = row % LL;
    int b = bh / HH, h = bh % HH;
    u64* dst = (u64*)(g_o + ((size_t)(b * LL + q)) * EE + h * DD);
    dst[lane] = acc;
}

// ---------------------------------------------------------------------------
// kernel_launch
// ---------------------------------------------------------------------------
extern "C" void kernel_launch(void* const* d_in, const int* in_sizes, int n_in,
                              void* d_out, int out_size)
{
    const float* values = (const float*)d_in[0];
    const float* keys   = (const float*)d_in[1];
    const float* query  = (const float*)d_in[2];
    const int*   mask   = (const int*)d_in[3];
    const float* Wv = (const float*)d_in[4];
    const float* bv = (const float*)d_in[5];
    const float* Wk = (const float*)d_in[6];
    const float* bk = (const float*)d_in[7];
    const float* Wq = (const float*)d_in[8];
    const float* bq = (const float*)d_in[9];
    const float* Wo = (const float*)d_in[10];
    const float* bo = (const float*)d_in[11];
    float* out = (float*)d_out;

    pack_mask_kernel<<<(Bb * LL * LL) / 256, 256>>>(mask);

    dim3 qkv_grid(GN / BNt, GM / BMt, 3);    // (8, 32, 3) = 768 CTAs
    qkv_gemm_kernel<<<qkv_grid, 256>>>(values, keys, query, Wv, bv, Wk, bk, Wq, bq);

    attn_kernel<<<dim3(LL / BQ, Bb * HH, SPLIT), 128>>>();   // 1024 CTAs

    combine_kernel<<<RTOT / 8, 256>>>();

    dim3 o_grid(GN / BNt, GM / BMt);         // (8, 32) = 256 CTAs
    out_gemm_kernel<<<o_grid, 256>>>(Wo, bo, out);
}